// round 9
// baseline (speedup 1.0000x reference)
#include <cuda_runtime.h>
#include <cstdint>
#include <math.h>

#define NWIN 2048
#define TT   64
#define CC   256
#define MD   128
#define HID  1024
#define NTOK (NWIN*TT)   // 131072

// ---------------- scratch ----------------
__device__ __align__(16) float g_xn[NTOK*CC];
__device__ __align__(16) float g_qkv[NTOK*768];
__device__ __align__(16) float g_ce[NTOK*MD];
__device__ __align__(16) float g_att[NTOK*CC];
__device__ __align__(16) float g_attce[NTOK*MD];
__device__ __align__(16) float g_h[NTOK*HID];
__device__ __align__(16) float g_h2[NTOK*HID];
__device__ __align__(16) float g_Wqkv[CC*768];
__device__ __align__(16) float g_bqkv[768];
__device__ __align__(16) float g_Wp[256*256];
__device__ __align__(16) float g_Wm[128*128];
__device__ __align__(16) float g_W1[256*1024];
__device__ __align__(16) float g_W2[1024*256];

__device__ __forceinline__ int win2glob(int row){
    int w = row >> 6, t = row & 63;
    int b = w >> 8, wi = w & 255;
    int gy = ((wi >> 4) << 3) + (t >> 3);
    int gx = ((wi & 15) << 3) + (t & 7);
    return (b*128 + gy)*128 + gx;
}

// round fp32 -> tf32-representable fp32 (rna)
__device__ __forceinline__ float tf32r(float f){
    uint32_t u; asm("cvt.rna.tf32.f32 %0, %1;" : "=r"(u) : "f"(f));
    return __uint_as_float(u);
}
__device__ __forceinline__ void mma_tf32(float* c, const uint32_t* a, const uint32_t* b){
    asm volatile("mma.sync.aligned.m16n8k8.row.col.f32.tf32.tf32.f32 "
        "{%0,%1,%2,%3}, {%4,%5,%6,%7}, {%8,%9}, {%0,%1,%2,%3};"
        : "+f"(c[0]), "+f"(c[1]), "+f"(c[2]), "+f"(c[3])
        : "r"(a[0]), "r"(a[1]), "r"(a[2]), "r"(a[3]), "r"(b[0]), "r"(b[1]));
}
__device__ __forceinline__ uint32_t smem_u32(const void* p){
    uint32_t a;
    asm("{ .reg .u64 t; cvta.to.shared.u64 t, %1; cvt.u32.u64 %0, t; }" : "=r"(a) : "l"(p));
    return a;
}
__device__ __forceinline__ void cpasync16(uint32_t dst, const void* src){
    asm volatile("cp.async.ca.shared.global [%0], [%1], 16;" :: "r"(dst), "l"(src));
}
#define CP_COMMIT() asm volatile("cp.async.commit_group;" ::: "memory")

// ---------------- weight prep ----------------
__global__ void prep_wqkv(const float* __restrict__ Wq, const float* __restrict__ bq,
                          const float* __restrict__ Wkv, const float* __restrict__ bkv){
    int i = blockIdx.x*blockDim.x + threadIdx.x;   // 768*256
    int k = i / 768, n = i % 768;
    g_Wqkv[i] = tf32r((n < 256) ? Wq[k*256 + n] : Wkv[k*512 + (n - 256)]);
    if (i < 768) g_bqkv[i] = (i < 256) ? bq[i] : bkv[i - 256];
}
__global__ void round_copy(const float* __restrict__ in, float* __restrict__ out, int n){
    int i = blockIdx.x*blockDim.x + threadIdx.x;
    if (i < n) out[i] = tf32r(in[i]);
}

// ---------------- LayerNorm (tf32-rounded output) ----------------
template<bool GATHER>
__global__ void ln_kernel(const float* __restrict__ x, float* __restrict__ out,
                          const float* __restrict__ gg, const float* __restrict__ bb){
    int row  = blockIdx.x*8 + (threadIdx.x >> 5);
    int lane = threadIdx.x & 31;
    const float* src = x + (size_t)(GATHER ? win2glob(row) : row)*CC;
    float v[8]; float s = 0.f;
    #pragma unroll
    for(int i=0;i<8;i++){ v[i] = src[lane + i*32]; s += v[i]; }
    #pragma unroll
    for(int o=16;o;o>>=1) s += __shfl_xor_sync(0xffffffffu, s, o);
    float mean = s * (1.f/CC);
    float s2 = 0.f;
    #pragma unroll
    for(int i=0;i<8;i++){ float d = v[i]-mean; s2 += d*d; }
    #pragma unroll
    for(int o=16;o;o>>=1) s2 += __shfl_xor_sync(0xffffffffu, s2, o);
    float rstd = rsqrtf(s2*(1.f/CC) + 1e-5f);
    float* dst = out + (size_t)row*CC;
    #pragma unroll
    for(int i=0;i<8;i++){
        int c = lane + i*32;
        dst[c] = tf32r((v[i]-mean)*rstd*gg[c] + bb[c]);
    }
}

// ---------------- coordinate embedding ----------------
__global__ void ce_kernel(const float* __restrict__ cor, const float* __restrict__ Wce,
                          const float* __restrict__ bce){
    int i = blockIdx.x*blockDim.x + threadIdx.x;
    int row = i >> 7, m = i & 127;
    int gp = win2glob(row)*2;
    g_ce[i] = cor[gp]*Wce[m] + cor[gp+1]*Wce[MD+m] + bce[m];
}

// ---------------- attention (tf32-rounded outputs) ----------------
__global__ void attn_kernel(){
    int blk = blockIdx.x;
    int w = blk >> 3, h = blk & 7;
    int pw = (w + 1024) & 2047;
    int t = threadIdx.x;
    __shared__ float ks[64*32];
    __shared__ float vs[64*32];
    __shared__ float cs[64*16];
    const float* kb = g_qkv + (size_t)pw*64*768 + 256 + h*32;
    const float* vb = g_qkv + (size_t)pw*64*768 + 512 + h*32;
    const float* cb = g_ce  + (size_t)w*64*128 + h*16;
    #pragma unroll
    for(int idx=t; idx<2048; idx+=64){
        int r = idx>>5, d = idx&31;
        ks[idx] = kb[(size_t)r*768 + d];
        vs[idx] = vb[(size_t)r*768 + d];
    }
    #pragma unroll
    for(int idx=t; idx<1024; idx+=64){
        int r = idx>>4, d = idx&15;
        cs[idx] = cb[(size_t)r*128 + d];
    }
    __syncthreads();

    const float scale = 0.17677669529663687f;
    float q[32];
    const float* qb = g_qkv + ((size_t)w*64 + t)*768 + h*32;
    #pragma unroll
    for(int d=0;d<32;d++) q[d] = qb[d]*scale;

    float s[64];
    #pragma unroll
    for(int j=0;j<64;j++){
        float a = 0.f;
        #pragma unroll
        for(int d=0;d<32;d++) a = fmaf(q[d], ks[j*32+d], a);
        s[j] = a;
    }
    float m = -1e30f;
    #pragma unroll
    for(int j=0;j<64;j++) m = fmaxf(m, s[j]);
    float sum = 0.f;
    #pragma unroll
    for(int j=0;j<64;j++){ s[j] = expf(s[j]-m); sum += s[j]; }
    float inv = 1.f/sum;

    float av[32];
    #pragma unroll
    for(int d=0;d<32;d++) av[d] = 0.f;
    #pragma unroll
    for(int j=0;j<64;j++){
        float p = s[j];
        #pragma unroll
        for(int d=0;d<32;d++) av[d] = fmaf(p, vs[j*32+d], av[d]);
    }
    float ac[16];
    #pragma unroll
    for(int d=0;d<16;d++) ac[d] = 0.f;
    #pragma unroll
    for(int j=0;j<64;j++){
        float p = s[j];
        #pragma unroll
        for(int d=0;d<16;d++) ac[d] = fmaf(p, cs[j*16+d], ac[d]);
    }

    float* ao = g_att + ((size_t)w*64 + t)*256 + h*32;
    #pragma unroll
    for(int d=0;d<32;d++) ao[d] = tf32r(av[d]*inv);
    const float* ceq = g_ce + ((size_t)w*64 + t)*128 + h*16;
    float* co = g_attce + ((size_t)w*64 + t)*128 + h*16;
    #pragma unroll
    for(int d=0;d<16;d++) co[d] = tf32r(ac[d]*inv - ceq[d]);
}

// ---------------- TF32 mma.sync GEMM: 256x128 block, 64x64 warp tile ----------------
// C[M,N] = A[M,K] @ W[K,N] + bias. W K-major. Inputs pre-rounded to tf32.
// MODE 0: store; 1: scatter+residual(add); 2: scatter; 3: out += val
#define APITCH 36
#define BPITCH 136
#define AS_F (256*APITCH)          // 9216 floats
#define BS_F (32*BPITCH)           // 4352 floats
#define ST_F (AS_F + BS_F)         // 13568 floats = 54272 B
#define NSTAGE 4                   // 217088 B dynamic smem

template<int MODE>
__global__ void __launch_bounds__(256) gemm_mma(const float* __restrict__ A,
        const float* __restrict__ W, const float* __restrict__ bias,
        float* __restrict__ out, int K, int Ntot, const float* __restrict__ add){
    extern __shared__ float sm[];

    int tid = threadIdx.x;
    int wid = tid >> 5, lane = tid & 31;
    int g = lane >> 2, tg = lane & 3;
    int bm = blockIdx.y << 8, bn = blockIdx.x << 7;
    int mBase = (wid & 3) << 6;       // 0,64,128,192
    int nBase = (wid >> 2) << 6;      // 0,64

    float c[4][8][4];
    #pragma unroll
    for(int i=0;i<4;i++)
        #pragma unroll
        for(int j=0;j<8;j++)
            #pragma unroll
            for(int q=0;q<4;q++) c[i][j][q] = 0.f;

    int nch = K >> 5;
    uint32_t smB = smem_u32(sm);

    auto issue = [&](int ch){
        uint32_t st = smB + (uint32_t)((ch % NSTAGE) * ST_F) * 4u;
        int k0 = ch << 5;
        #pragma unroll
        for(int i=0;i<8;i++){
            int idx = i*256 + tid;
            int ar = idx >> 3, ac4 = (idx & 7) << 2;
            cpasync16(st + (uint32_t)(ar*APITCH + ac4)*4u,
                      A + (size_t)(bm + ar)*K + k0 + ac4);
        }
        #pragma unroll
        for(int i=0;i<4;i++){
            int idx = i*256 + tid;
            int br = idx >> 5, bc4 = (idx & 31) << 2;
            cpasync16(st + (uint32_t)(AS_F + br*BPITCH + bc4)*4u,
                      W + (size_t)(k0 + br)*Ntot + bn + bc4);
        }
        CP_COMMIT();
    };

    issue(0);
    if (nch > 1) issue(1); else CP_COMMIT();
    if (nch > 2) issue(2); else CP_COMMIT();

    for(int ch=0; ch<nch; ch++){
        asm volatile("cp.async.wait_group 2;" ::: "memory");
        __syncthreads();
        if (ch + 3 < nch) issue(ch + 3);
        else CP_COMMIT();

        const float* Asf = sm + (ch % NSTAGE) * ST_F;
        const float* Bsf = Asf + AS_F;

        #pragma unroll
        for(int ks=0; ks<4; ks++){
            int k = ks << 3;
            uint32_t af[4][4], bf[8][2];
            #pragma unroll
            for(int mt=0; mt<4; mt++){
                int r0 = mBase + (mt<<4) + g;
                af[mt][0] = __float_as_uint(Asf[ r0    *APITCH + k + tg    ]);
                af[mt][1] = __float_as_uint(Asf[(r0+8) *APITCH + k + tg    ]);
                af[mt][2] = __float_as_uint(Asf[ r0    *APITCH + k + tg + 4]);
                af[mt][3] = __float_as_uint(Asf[(r0+8) *APITCH + k + tg + 4]);
            }
            #pragma unroll
            for(int j=0; j<8; j++){
                int n = nBase + (j<<3) + g;
                bf[j][0] = __float_as_uint(Bsf[(k + tg    )*BPITCH + n]);
                bf[j][1] = __float_as_uint(Bsf[(k + tg + 4)*BPITCH + n]);
            }
            #pragma unroll
            for(int mt=0; mt<4; mt++)
                #pragma unroll
                for(int j=0; j<8; j++)
                    mma_tf32(c[mt][j], af[mt], bf[j]);
        }
    }

    // epilogue: direct global stores (float2 per fragment half)
    #pragma unroll
    for(int mt=0; mt<4; mt++){
        #pragma unroll
        for(int half=0; half<2; half++){
            int grow = bm + mBase + (mt<<4) + g + (half<<3);
            int orow = (MODE==1 || MODE==2) ? win2glob(grow) : grow;
            #pragma unroll
            for(int j=0; j<8; j++){
                int cn = bn + nBase + (j<<3) + (tg<<1);
                float2 bb = *(const float2*)(bias + cn);
                float v0 = c[mt][j][half*2+0] + bb.x;
                float v1 = c[mt][j][half*2+1] + bb.y;
                if (MODE == 0){
                    *(float2*)(out + (size_t)grow*Ntot + cn) = make_float2(v0, v1);
                } else if (MODE == 1){
                    float2 ad = *(const float2*)(add + (size_t)grow*Ntot + cn);
                    *(float2*)(out + (size_t)orow*Ntot + cn) = make_float2(v0+ad.x, v1+ad.y);
                } else if (MODE == 2){
                    *(float2*)(out + (size_t)orow*Ntot + cn) = make_float2(v0, v1);
                } else {
                    float2 o = *(float2*)(out + (size_t)grow*Ntot + cn);
                    *(float2*)(out + (size_t)grow*Ntot + cn) = make_float2(o.x+v0, o.y+v1);
                }
            }
        }
    }
}
#define GEMM_SMEM (NSTAGE*ST_F*4)

// ---------------- depthwise 3x3 conv + GELU (tf32-rounded output) ----------------
__global__ void dwconv_gelu(const float* __restrict__ Wdw, const float* __restrict__ bdw){
    int i = blockIdx.x*blockDim.x + threadIdx.x;  // NTOK*HID/4 threads
    int ch = i & 1023;
    int r  = i >> 10;
    int x0 = (r & 31) << 2;        // 0,4,...,124
    int yg = (r >> 5) & 127;
    int b  = r >> 12;
    float w[9];
    #pragma unroll
    for(int t=0;t<9;t++) w[t] = Wdw[t*1024 + ch];
    float bias = bdw[ch];
    float acc[4] = {bias, bias, bias, bias};
    #pragma unroll
    for(int ky=0;ky<3;ky++){
        int yy = yg + ky - 1;
        if (yy < 0 || yy > 127) continue;
        const float* rp = g_h + ((size_t)((b*128+yy)*128))*1024 + ch;
        float v[6];
        #pragma unroll
        for(int dx=0;dx<6;dx++){
            int xx = x0 + dx - 1;
            v[dx] = (xx >= 0 && xx < 128) ? rp[(size_t)xx*1024] : 0.f;
        }
        #pragma unroll
        for(int o=0;o<4;o++)
            #pragma unroll
            for(int kx=0;kx<3;kx++)
                acc[o] = fmaf(v[o+kx], w[ky*3+kx], acc[o]);
    }
    float* op = g_h2 + ((size_t)((b*128+yg)*128 + x0))*1024 + ch;
    #pragma unroll
    for(int o=0;o<4;o++)
        op[(size_t)o*1024] = tf32r(0.5f*acc[o]*(1.f + erff(acc[o]*0.70710678118654752f)));
}

// ---------------- launch ----------------
extern "C" void kernel_launch(void* const* d_in, const int* in_sizes, int n_in,
                              void* d_out, int out_size){
    const float* x     = (const float*)d_in[0];
    const float* cor   = (const float*)d_in[1];
    const float* g1    = (const float*)d_in[2];
    const float* b1    = (const float*)d_in[3];
    const float* Wq    = (const float*)d_in[4];
    const float* bq    = (const float*)d_in[5];
    const float* Wkv   = (const float*)d_in[6];
    const float* bkv   = (const float*)d_in[7];
    const float* Wproj = (const float*)d_in[8];
    const float* bproj = (const float*)d_in[9];
    const float* Wce   = (const float*)d_in[10];
    const float* bce   = (const float*)d_in[11];
    const float* Wmp   = (const float*)d_in[12];
    const float* bmp   = (const float*)d_in[13];
    const float* g2    = (const float*)d_in[14];
    const float* b2    = (const float*)d_in[15];
    const float* Wfc1  = (const float*)d_in[16];
    const float* bfc1  = (const float*)d_in[17];
    const float* Wdw   = (const float*)d_in[18];
    const float* bdw   = (const float*)d_in[19];
    const float* Wfc2  = (const float*)d_in[20];
    const float* bfc2  = (const float*)d_in[21];

    float* out  = (float*)d_out;
    float* xout = out;
    float* mout = out + (size_t)NTOK*CC;

    float *p_xn, *p_qkv, *p_att, *p_attce, *p_h, *p_h2, *p_Wqkv, *p_bqkv;
    float *p_Wp, *p_Wm, *p_W1, *p_W2;
    cudaGetSymbolAddress((void**)&p_xn,    g_xn);
    cudaGetSymbolAddress((void**)&p_qkv,   g_qkv);
    cudaGetSymbolAddress((void**)&p_att,   g_att);
    cudaGetSymbolAddress((void**)&p_attce, g_attce);
    cudaGetSymbolAddress((void**)&p_h,     g_h);
    cudaGetSymbolAddress((void**)&p_h2,    g_h2);
    cudaGetSymbolAddress((void**)&p_Wqkv,  g_Wqkv);
    cudaGetSymbolAddress((void**)&p_bqkv,  g_bqkv);
    cudaGetSymbolAddress((void**)&p_Wp,    g_Wp);
    cudaGetSymbolAddress((void**)&p_Wm,    g_Wm);
    cudaGetSymbolAddress((void**)&p_W1,    g_W1);
    cudaGetSymbolAddress((void**)&p_W2,    g_W2);

    cudaFuncSetAttribute(gemm_mma<0>, cudaFuncAttributeMaxDynamicSharedMemorySize, GEMM_SMEM);
    cudaFuncSetAttribute(gemm_mma<1>, cudaFuncAttributeMaxDynamicSharedMemorySize, GEMM_SMEM);
    cudaFuncSetAttribute(gemm_mma<2>, cudaFuncAttributeMaxDynamicSharedMemorySize, GEMM_SMEM);
    cudaFuncSetAttribute(gemm_mma<3>, cudaFuncAttributeMaxDynamicSharedMemorySize, GEMM_SMEM);

    prep_wqkv<<<768, 256>>>(Wq, bq, Wkv, bkv);
    round_copy<<<256, 256>>>(Wproj, p_Wp, 256*256);
    round_copy<<<64, 256>>>(Wmp, p_Wm, 128*128);
    round_copy<<<1024, 256>>>(Wfc1, p_W1, 256*1024);
    round_copy<<<1024, 256>>>(Wfc2, p_W2, 1024*256);

    ln_kernel<true><<<NTOK/8, 256>>>(x, p_xn, g1, b1);
    ce_kernel<<<(NTOK*MD)/256, 256>>>(cor, Wce, bce);
    gemm_mma<0><<<dim3(6, 512), 256, GEMM_SMEM>>>(p_xn, p_Wqkv, p_bqkv, p_qkv, 256, 768, nullptr);
    attn_kernel<<<NWIN*8, 64>>>();
    gemm_mma<1><<<dim3(2, 512), 256, GEMM_SMEM>>>(p_att, p_Wp, bproj, xout, 256, 256, p_xn);
    gemm_mma<2><<<dim3(1, 512), 256, GEMM_SMEM>>>(p_attce, p_Wm, bmp, mout, 128, 128, nullptr);
    ln_kernel<false><<<NTOK/8, 256>>>(xout, p_att, g2, b2);
    gemm_mma<0><<<dim3(8, 512), 256, GEMM_SMEM>>>(p_att, p_W1, bfc1, p_h, 256, 1024, nullptr);
    dwconv_gelu<<<(NTOK*HID/4)/256, 256>>>(Wdw, bdw);
    gemm_mma<3><<<dim3(2, 512), 256, GEMM_SMEM>>>(p_h2, p_W2, bfc2, xout, 1024, 256, nullptr);
}

// round 10
// speedup vs baseline: 1.3899x; 1.3899x over previous
#include <cuda_runtime.h>
#include <cuda_fp16.h>
#include <cstdint>
#include <math.h>

#define NWIN 2048
#define TT   64
#define CC   256
#define MD   128
#define HID  1024
#define NTOK (NWIN*TT)   // 131072

// ---------------- scratch ----------------
__device__ __align__(16) __half g_xn[NTOK*CC];
__device__ __align__(16) float  g_qkv[NTOK*768];
__device__ __align__(16) float  g_ce[NTOK*MD];
__device__ __align__(16) __half g_att[NTOK*CC];     // attn out; later LN2 out
__device__ __align__(16) __half g_attce[NTOK*MD];
__device__ __align__(16) __half g_h[NTOK*HID];
__device__ __align__(16) __half g_h2[NTOK*HID];
__device__ __align__(16) __half g_Wqkv[768*256];    // [N][K]
__device__ __align__(16) float  g_bqkv[768];
__device__ __align__(16) __half g_Wp[256*256];      // [N][K]
__device__ __align__(16) __half g_Wm[128*128];
__device__ __align__(16) __half g_W1[1024*256];
__device__ __align__(16) __half g_W2[256*1024];

__device__ __forceinline__ int win2glob(int row){
    int w = row >> 6, t = row & 63;
    int b = w >> 8, wi = w & 255;
    int gy = ((wi >> 4) << 3) + (t >> 3);
    int gx = ((wi & 15) << 3) + (t & 7);
    return (b*128 + gy)*128 + gx;
}

__device__ __forceinline__ void mma_f16(float* c, const uint32_t* a, const uint32_t* b){
    asm volatile("mma.sync.aligned.m16n8k16.row.col.f32.f16.f16.f32 "
        "{%0,%1,%2,%3}, {%4,%5,%6,%7}, {%8,%9}, {%0,%1,%2,%3};"
        : "+f"(c[0]), "+f"(c[1]), "+f"(c[2]), "+f"(c[3])
        : "r"(a[0]), "r"(a[1]), "r"(a[2]), "r"(a[3]), "r"(b[0]), "r"(b[1]));
}
__device__ __forceinline__ uint32_t smem_u32(const void* p){
    uint32_t a;
    asm("{ .reg .u64 t; cvta.to.shared.u64 t, %1; cvt.u32.u64 %0, t; }" : "=r"(a) : "l"(p));
    return a;
}
__device__ __forceinline__ void cpasync16(uint32_t dst, const void* src){
    asm volatile("cp.async.ca.shared.global [%0], [%1], 16;" :: "r"(dst), "l"(src));
}
#define CP_COMMIT() asm volatile("cp.async.commit_group;" ::: "memory")

// ---------------- weight prep: transpose+fp16 ----------------
__global__ void prep_wqkv(const float* __restrict__ Wq, const float* __restrict__ bq,
                          const float* __restrict__ Wkv, const float* __restrict__ bkv){
    int i = blockIdx.x*blockDim.x + threadIdx.x;   // 768*256
    int n = i >> 8, k = i & 255;
    float v = (n < 256) ? Wq[k*256 + n] : Wkv[k*512 + (n - 256)];
    g_Wqkv[i] = __float2half_rn(v);
    if (i < 768) g_bqkv[i] = (i < 256) ? bq[i] : bkv[i - 256];
}
__global__ void transpose_h(const float* __restrict__ in, __half* __restrict__ out, int K, int N){
    int i = blockIdx.x*blockDim.x + threadIdx.x;   // N*K
    int n = i / K, k = i % K;
    out[i] = __float2half_rn(in[(size_t)k*N + n]);
}

// ---------------- LayerNorm (fp16 output) ----------------
template<bool GATHER>
__global__ void ln_kernel(const float* __restrict__ x, __half* __restrict__ out,
                          const float* __restrict__ gg, const float* __restrict__ bb){
    int row  = blockIdx.x*8 + (threadIdx.x >> 5);
    int lane = threadIdx.x & 31;
    const float* src = x + (size_t)(GATHER ? win2glob(row) : row)*CC;
    float v[8]; float s = 0.f;
    #pragma unroll
    for(int i=0;i<8;i++){ v[i] = src[lane + i*32]; s += v[i]; }
    #pragma unroll
    for(int o=16;o;o>>=1) s += __shfl_xor_sync(0xffffffffu, s, o);
    float mean = s * (1.f/CC);
    float s2 = 0.f;
    #pragma unroll
    for(int i=0;i<8;i++){ float d = v[i]-mean; s2 += d*d; }
    #pragma unroll
    for(int o=16;o;o>>=1) s2 += __shfl_xor_sync(0xffffffffu, s2, o);
    float rstd = rsqrtf(s2*(1.f/CC) + 1e-5f);
    __half* dst = out + (size_t)row*CC;
    #pragma unroll
    for(int i=0;i<8;i++){
        int c = lane + i*32;
        dst[c] = __float2half_rn((v[i]-mean)*rstd*gg[c] + bb[c]);
    }
}

// ---------------- coordinate embedding ----------------
__global__ void ce_kernel(const float* __restrict__ cor, const float* __restrict__ Wce,
                          const float* __restrict__ bce){
    int i = blockIdx.x*blockDim.x + threadIdx.x;
    int row = i >> 7, m = i & 127;
    int gp = win2glob(row)*2;
    g_ce[i] = cor[gp]*Wce[m] + cor[gp+1]*Wce[MD+m] + bce[m];
}

// ---------------- attention (fp16 outputs) ----------------
__global__ void attn_kernel(){
    int blk = blockIdx.x;
    int w = blk >> 3, h = blk & 7;
    int pw = (w + 1024) & 2047;
    int t = threadIdx.x;
    __shared__ float ks[64*32];
    __shared__ float vs[64*32];
    __shared__ float cs[64*16];
    const float* kb = g_qkv + (size_t)pw*64*768 + 256 + h*32;
    const float* vb = g_qkv + (size_t)pw*64*768 + 512 + h*32;
    const float* cb = g_ce  + (size_t)w*64*128 + h*16;
    #pragma unroll
    for(int idx=t; idx<2048; idx+=64){
        int r = idx>>5, d = idx&31;
        ks[idx] = kb[(size_t)r*768 + d];
        vs[idx] = vb[(size_t)r*768 + d];
    }
    #pragma unroll
    for(int idx=t; idx<1024; idx+=64){
        int r = idx>>4, d = idx&15;
        cs[idx] = cb[(size_t)r*128 + d];
    }
    __syncthreads();

    const float scale = 0.17677669529663687f;
    float q[32];
    const float* qb = g_qkv + ((size_t)w*64 + t)*768 + h*32;
    #pragma unroll
    for(int d=0;d<32;d++) q[d] = qb[d]*scale;

    float s[64];
    #pragma unroll
    for(int j=0;j<64;j++){
        float a = 0.f;
        #pragma unroll
        for(int d=0;d<32;d++) a = fmaf(q[d], ks[j*32+d], a);
        s[j] = a;
    }
    float m = -1e30f;
    #pragma unroll
    for(int j=0;j<64;j++) m = fmaxf(m, s[j]);
    float sum = 0.f;
    #pragma unroll
    for(int j=0;j<64;j++){ s[j] = expf(s[j]-m); sum += s[j]; }
    float inv = 1.f/sum;

    float av[32];
    #pragma unroll
    for(int d=0;d<32;d++) av[d] = 0.f;
    #pragma unroll
    for(int j=0;j<64;j++){
        float p = s[j];
        #pragma unroll
        for(int d=0;d<32;d++) av[d] = fmaf(p, vs[j*32+d], av[d]);
    }
    float ac[16];
    #pragma unroll
    for(int d=0;d<16;d++) ac[d] = 0.f;
    #pragma unroll
    for(int j=0;j<64;j++){
        float p = s[j];
        #pragma unroll
        for(int d=0;d<16;d++) ac[d] = fmaf(p, cs[j*16+d], ac[d]);
    }

    __half* ao = g_att + ((size_t)w*64 + t)*256 + h*32;
    #pragma unroll
    for(int d=0;d<32;d++) ao[d] = __float2half_rn(av[d]*inv);
    const float* ceq = g_ce + ((size_t)w*64 + t)*128 + h*16;
    __half* co = g_attce + ((size_t)w*64 + t)*128 + h*16;
    #pragma unroll
    for(int d=0;d<16;d++) co[d] = __float2half_rn(ac[d]*inv - ceq[d]);
}

// ---------------- FP16 mma.sync GEMM: 128x128 block, chunk K=64, 4-stage ----------------
// C[M,N] = A[M,K] @ Wt^T + bias; A [M][K] fp16 row-major, Wt [N][K] fp16 row-major.
// MODE 0: store fp32; 1: scatter+residual(half add)->fp32; 2: scatter fp32;
// MODE 3: fp32 out += val; 4: store fp16
#define KCH 64
#define PITCHH 72                 // halves per row
#define AS_H (128*PITCHH)         // 9216 halves per A tile
#define ST_H (2*AS_H)             // A + B
#define NSTAGE 4                  // 4*36864 B = 147456 B

template<int MODE>
__global__ void __launch_bounds__(256) gemm_mma(const __half* __restrict__ A,
        const __half* __restrict__ Wt, const float* __restrict__ bias,
        void* __restrict__ outv, int K, int Ntot, const __half* __restrict__ add){
    extern __shared__ __half smh[];

    int tid = threadIdx.x;
    int wid = tid >> 5, lane = tid & 31;
    int g = lane >> 2, tg = lane & 3;
    int bm = blockIdx.y << 7, bn = blockIdx.x << 7;
    int mBase = (wid & 3) << 5;       // 0,32,64,96
    int nBase = (wid >> 2) << 6;      // 0,64

    float c[2][8][4];
    #pragma unroll
    for(int i=0;i<2;i++)
        #pragma unroll
        for(int j=0;j<8;j++)
            #pragma unroll
            for(int q=0;q<4;q++) c[i][j][q] = 0.f;

    int nch = K / KCH;
    uint32_t smB = smem_u32(smh);

    auto issue = [&](int ch){
        uint32_t st = smB + (uint32_t)((ch % NSTAGE) * ST_H) * 2u;
        int k0 = ch * KCH;
        #pragma unroll
        for(int i=0;i<4;i++){
            int idx = i*256 + tid;
            int row = idx >> 3, seg = (idx & 7) << 3;   // 8 halves per cp
            cpasync16(st + (uint32_t)(row*PITCHH + seg)*2u,
                      A + (size_t)(bm + row)*K + k0 + seg);
            cpasync16(st + (uint32_t)(AS_H + row*PITCHH + seg)*2u,
                      Wt + (size_t)(bn + row)*K + k0 + seg);
        }
        CP_COMMIT();
    };

    issue(0);
    if (nch > 1) issue(1); else CP_COMMIT();
    if (nch > 2) issue(2); else CP_COMMIT();

    for(int ch=0; ch<nch; ch++){
        asm volatile("cp.async.wait_group 2;" ::: "memory");
        __syncthreads();
        if (ch + 3 < nch) issue(ch + 3);
        else CP_COMMIT();

        const uint32_t* Au = (const uint32_t*)(smh + (size_t)(ch % NSTAGE) * ST_H);
        const uint32_t* Bu = Au + AS_H/2;

        uint32_t afA[2][4], bfA[8][2], afB[2][4], bfB[8][2];

        // k in halves (0,16,32,48); u32 col index = k/2 + tg (+4 for hi-half)
        #define LOAD_FRAGS(kk, af, bf) do{                               \
            int kc = (kk) >> 1;                                          \
            _Pragma("unroll")                                            \
            for(int mt=0; mt<2; mt++){                                   \
                int r0 = mBase + (mt<<4) + g;                            \
                af[mt][0] = Au[ r0   *(PITCHH/2) + kc + tg    ];         \
                af[mt][1] = Au[(r0+8)*(PITCHH/2) + kc + tg    ];         \
                af[mt][2] = Au[ r0   *(PITCHH/2) + kc + tg + 4];         \
                af[mt][3] = Au[(r0+8)*(PITCHH/2) + kc + tg + 4];         \
            }                                                            \
            _Pragma("unroll")                                            \
            for(int j=0; j<8; j++){                                      \
                int n_ = nBase + (j<<3) + g;                             \
                bf[j][0] = Bu[n_*(PITCHH/2) + kc + tg    ];              \
                bf[j][1] = Bu[n_*(PITCHH/2) + kc + tg + 4];              \
            } }while(0)

        #define DO_MMA(af, bf) do{                                       \
            _Pragma("unroll")                                            \
            for(int mt=0; mt<2; mt++)                                    \
                _Pragma("unroll")                                        \
                for(int j=0; j<8; j++)                                   \
                    mma_f16(c[mt][j], af[mt], bf[j]);                    \
            }while(0)

        LOAD_FRAGS(0, afA, bfA);
        LOAD_FRAGS(16, afB, bfB);  DO_MMA(afA, bfA);
        LOAD_FRAGS(32, afA, bfA);  DO_MMA(afB, bfB);
        LOAD_FRAGS(48, afB, bfB);  DO_MMA(afA, bfA);
        DO_MMA(afB, bfB);

        #undef LOAD_FRAGS
        #undef DO_MMA
    }

    float* outf = (float*)outv;
    __half* outh = (__half*)outv;
    #pragma unroll
    for(int mt=0; mt<2; mt++){
        #pragma unroll
        for(int half=0; half<2; half++){
            int grow = bm + mBase + (mt<<4) + g + (half<<3);
            int orow = (MODE==1 || MODE==2) ? win2glob(grow) : grow;
            #pragma unroll
            for(int j=0; j<8; j++){
                int cn = bn + nBase + (j<<3) + (tg<<1);
                float2 bb = *(const float2*)(bias + cn);
                float v0 = c[mt][j][half*2+0] + bb.x;
                float v1 = c[mt][j][half*2+1] + bb.y;
                if (MODE == 0){
                    *(float2*)(outf + (size_t)grow*Ntot + cn) = make_float2(v0, v1);
                } else if (MODE == 1){
                    __half2 ad = *(const __half2*)(add + (size_t)grow*Ntot + cn);
                    *(float2*)(outf + (size_t)orow*Ntot + cn) =
                        make_float2(v0 + __half2float(ad.x), v1 + __half2float(ad.y));
                } else if (MODE == 2){
                    *(float2*)(outf + (size_t)orow*Ntot + cn) = make_float2(v0, v1);
                } else if (MODE == 3){
                    float2 o = *(float2*)(outf + (size_t)grow*Ntot + cn);
                    *(float2*)(outf + (size_t)grow*Ntot + cn) = make_float2(o.x+v0, o.y+v1);
                } else {
                    *(__half2*)(outh + (size_t)grow*Ntot + cn) =
                        __floats2half2_rn(v0, v1);
                }
            }
        }
    }
}
#define GEMM_SMEM (NSTAGE*ST_H*2)

// ---------------- depthwise 3x3 conv + GELU (fp16 in/out) ----------------
__global__ void dwconv_gelu(const float* __restrict__ Wdw, const float* __restrict__ bdw){
    int i = blockIdx.x*blockDim.x + threadIdx.x;  // NTOK*HID/4 threads
    int ch = i & 1023;
    int r  = i >> 10;
    int x0 = (r & 31) << 2;        // 0,4,...,124
    int yg = (r >> 5) & 127;
    int b  = r >> 12;
    float w[9];
    #pragma unroll
    for(int t=0;t<9;t++) w[t] = Wdw[t*1024 + ch];
    float bias = bdw[ch];
    float acc[4] = {bias, bias, bias, bias};
    #pragma unroll
    for(int ky=0;ky<3;ky++){
        int yy = yg + ky - 1;
        if (yy < 0 || yy > 127) continue;
        const __half* rp = g_h + ((size_t)((b*128+yy)*128))*1024 + ch;
        float v[6];
        #pragma unroll
        for(int dx=0;dx<6;dx++){
            int xx = x0 + dx - 1;
            v[dx] = (xx >= 0 && xx < 128) ? __half2float(rp[(size_t)xx*1024]) : 0.f;
        }
        #pragma unroll
        for(int o=0;o<4;o++)
            #pragma unroll
            for(int kx=0;kx<3;kx++)
                acc[o] = fmaf(v[o+kx], w[ky*3+kx], acc[o]);
    }
    __half* op = g_h2 + ((size_t)((b*128+yg)*128 + x0))*1024 + ch;
    #pragma unroll
    for(int o=0;o<4;o++)
        op[(size_t)o*1024] = __float2half_rn(0.5f*acc[o]*(1.f + erff(acc[o]*0.70710678118654752f)));
}

// ---------------- launch ----------------
extern "C" void kernel_launch(void* const* d_in, const int* in_sizes, int n_in,
                              void* d_out, int out_size){
    const float* x     = (const float*)d_in[0];
    const float* cor   = (const float*)d_in[1];
    const float* g1    = (const float*)d_in[2];
    const float* b1    = (const float*)d_in[3];
    const float* Wq    = (const float*)d_in[4];
    const float* bq    = (const float*)d_in[5];
    const float* Wkv   = (const float*)d_in[6];
    const float* bkv   = (const float*)d_in[7];
    const float* Wproj = (const float*)d_in[8];
    const float* bproj = (const float*)d_in[9];
    const float* Wce   = (const float*)d_in[10];
    const float* bce   = (const float*)d_in[11];
    const float* Wmp   = (const float*)d_in[12];
    const float* bmp   = (const float*)d_in[13];
    const float* g2    = (const float*)d_in[14];
    const float* b2    = (const float*)d_in[15];
    const float* Wfc1  = (const float*)d_in[16];
    const float* bfc1  = (const float*)d_in[17];
    const float* Wdw   = (const float*)d_in[18];
    const float* bdw   = (const float*)d_in[19];
    const float* Wfc2  = (const float*)d_in[20];
    const float* bfc2  = (const float*)d_in[21];

    float* out  = (float*)d_out;
    float* xout = out;
    float* mout = out + (size_t)NTOK*CC;

    __half *p_xn, *p_att, *p_attce, *p_h2, *p_Wqkv, *p_Wp, *p_Wm, *p_W1, *p_W2;
    float *p_qkv, *p_bqkv; __half *p_h;
    cudaGetSymbolAddress((void**)&p_xn,    g_xn);
    cudaGetSymbolAddress((void**)&p_qkv,   g_qkv);
    cudaGetSymbolAddress((void**)&p_att,   g_att);
    cudaGetSymbolAddress((void**)&p_attce, g_attce);
    cudaGetSymbolAddress((void**)&p_h,     g_h);
    cudaGetSymbolAddress((void**)&p_h2,    g_h2);
    cudaGetSymbolAddress((void**)&p_Wqkv,  g_Wqkv);
    cudaGetSymbolAddress((void**)&p_bqkv,  g_bqkv);
    cudaGetSymbolAddress((void**)&p_Wp,    g_Wp);
    cudaGetSymbolAddress((void**)&p_Wm,    g_Wm);
    cudaGetSymbolAddress((void**)&p_W1,    g_W1);
    cudaGetSymbolAddress((void**)&p_W2,    g_W2);

    cudaFuncSetAttribute(gemm_mma<0>, cudaFuncAttributeMaxDynamicSharedMemorySize, GEMM_SMEM);
    cudaFuncSetAttribute(gemm_mma<1>, cudaFuncAttributeMaxDynamicSharedMemorySize, GEMM_SMEM);
    cudaFuncSetAttribute(gemm_mma<2>, cudaFuncAttributeMaxDynamicSharedMemorySize, GEMM_SMEM);
    cudaFuncSetAttribute(gemm_mma<3>, cudaFuncAttributeMaxDynamicSharedMemorySize, GEMM_SMEM);
    cudaFuncSetAttribute(gemm_mma<4>, cudaFuncAttributeMaxDynamicSharedMemorySize, GEMM_SMEM);

    prep_wqkv<<<768, 256>>>(Wq, bq, Wkv, bkv);
    transpose_h<<<256, 256>>>(Wproj, p_Wp, 256, 256);
    transpose_h<<<64, 256>>>(Wmp, p_Wm, 128, 128);
    transpose_h<<<1024, 256>>>(Wfc1, p_W1, 256, 1024);
    transpose_h<<<1024, 256>>>(Wfc2, p_W2, 1024, 256);

    ln_kernel<true><<<NTOK/8, 256>>>(x, p_xn, g1, b1);
    ce_kernel<<<(NTOK*MD)/256, 256>>>(cor, Wce, bce);
    gemm_mma<0><<<dim3(6, 1024), 256, GEMM_SMEM>>>(p_xn, p_Wqkv, p_bqkv, p_qkv, 256, 768, nullptr);
    attn_kernel<<<NWIN*8, 64>>>();
    gemm_mma<1><<<dim3(2, 1024), 256, GEMM_SMEM>>>(p_att, p_Wp, bproj, xout, 256, 256, p_xn);
    gemm_mma<2><<<dim3(1, 1024), 256, GEMM_SMEM>>>(p_attce, p_Wm, bmp, mout, 128, 128, nullptr);
    ln_kernel<false><<<NTOK/8, 256>>>(xout, p_att, g2, b2);
    gemm_mma<4><<<dim3(8, 1024), 256, GEMM_SMEM>>>(p_att, p_W1, bfc1, p_h, 256, 1024, nullptr);
    dwconv_gelu<<<(NTOK*HID/4)/256, 256>>>(Wdw, bdw);
    gemm_mma<3><<<dim3(2, 1024), 256, GEMM_SMEM>>>(p_h2, p_W2, bfc2, xout, 1024, 256, nullptr);
}